// round 17
// baseline (speedup 1.0000x reference)
#include <cuda_runtime.h>
#include <cuda_fp16.h>
#include <math.h>
#include <stdint.h>

// Problem constants
#define BB 4
#define DD 768
#define GG 64
#define PP 256
#define HH 12
#define HD 64
#define GP (GG * PP)            // 16384
#define E3D (3 * DD)            // 2304
#define KK 768                  // K dim of both GEMMs
#define NT GP                   // N total of both GEMMs

// ---------------- scratch (allocation-free rule: __device__ globals) -------
__device__ __align__(256) __half g_qkv[(size_t)BB * E3D * GP];  // fp16 qkv
__device__ __align__(256) __half g_xT[(size_t)BB * GP * DD];    // x^T [B,N,K]
__device__ __align__(256) __half g_aT[(size_t)BB * GP * DD];    // att^T fp16
__device__ __align__(256) __half g_wq[(size_t)E3D * DD];        // w_qkv fp16
__device__ __align__(256) __half g_wp[(size_t)DD * DD];         // w_proj fp16
__device__ unsigned g_mask[(size_t)GG * PP * 8];   // packed keep-bits per (g,p)
__device__ int g_mask_dtype;                       // 0=u8,1=i32,2=f32,3=bf16

typedef unsigned long long ull;

// ---------------- small PTX helpers ----------------------------------------
__device__ __forceinline__ uint32_t smem_u32(const void* p) {
    uint32_t a;
    asm("{ .reg .u64 t; cvta.to.shared.u64 t, %1; cvt.u32.u64 %0, t; }"
        : "=r"(a) : "l"(p));
    return a;
}
__device__ __forceinline__ void ldsm4(uint32_t& r0, uint32_t& r1, uint32_t& r2,
                                      uint32_t& r3, uint32_t addr) {
    asm volatile("ldmatrix.sync.aligned.m8n8.x4.shared.b16 {%0,%1,%2,%3}, [%4];"
                 : "=r"(r0), "=r"(r1), "=r"(r2), "=r"(r3) : "r"(addr));
}
__device__ __forceinline__ void mma16816(float* c, const uint32_t* a, const uint32_t* b) {
    asm volatile(
        "mma.sync.aligned.m16n8k16.row.col.f32.f16.f16.f32 "
        "{%0,%1,%2,%3}, {%4,%5,%6,%7}, {%8,%9}, {%0,%1,%2,%3};"
        : "+f"(c[0]), "+f"(c[1]), "+f"(c[2]), "+f"(c[3])
        : "r"(a[0]), "r"(a[1]), "r"(a[2]), "r"(a[3]), "r"(b[0]), "r"(b[1]));
}
__device__ __forceinline__ uint32_t h2pack(float a, float b) {
    __half2 h = __floats2half2_rn(a, b);
    return *(uint32_t*)&h;
}
__device__ __forceinline__ void cpa16(uint32_t dst, const void* src) {
    asm volatile("cp.async.cg.shared.global [%0], [%1], 16;" :: "r"(dst), "l"(src));
}
#define CPA_COMMIT() asm volatile("cp.async.commit_group;" ::: "memory")
#define CPA_WAIT1()  asm volatile("cp.async.wait_group 1;" ::: "memory")
#define CPA_WAIT0()  asm volatile("cp.async.wait_group 0;" ::: "memory")

// Fast exp2 entirely on FMA/ALU pipes (magic-constant round, no cvt pipe).
__device__ __forceinline__ float fexp2(float t) {
    t = fmaxf(t, -120.0f);
    float r = t + 12582912.0f;             // round-to-nearest-int in mantissa
    float f = t - (r - 12582912.0f);       // [-0.5, 0.5]
    int   sc = (__float_as_int(r) - 0x4B3FFF81) << 23;  // (n+127)<<23
    float p = 1.5403530e-4f;
    p = fmaf(p, f, 1.3333558e-3f);
    p = fmaf(p, f, 9.6181291e-3f);
    p = fmaf(p, f, 5.5504109e-2f);
    p = fmaf(p, f, 2.4022651e-1f);
    p = fmaf(p, f, 6.9314718e-1f);
    p = fmaf(p, f, 1.0f);
    return p * __int_as_float(sc);
}

// ---------------------------------------------------------------------------
// Mask dtype detection + packing
// ---------------------------------------------------------------------------
__global__ void detect_mask_dtype(const unsigned* __restrict__ m) {
    if (threadIdx.x != 0 || blockIdx.x != 0) return;
    int dt = 1;
    for (int i = 0; i < 1024; i++) {
        unsigned w = m[i];
        if (w == 0x3F800000u) { dt = 2; break; }
        if ((w & 0xFFFFu) == 0x3F80u || (w >> 16) == 0x3F80u) { dt = 3; break; }
        if (w > 1u) { dt = 0; break; }
    }
    g_mask_dtype = dt;
}

__global__ void pack_mask(const void* __restrict__ mraw) {
    int idx = blockIdx.x * blockDim.x + threadIdx.x;
    if (idx >= GG * PP * 8) return;
    int row = idx >> 3, w = idx & 7;
    int dt = g_mask_dtype;
    size_t base = (size_t)row * PP + w * 32;
    unsigned bits = 0;
    for (int t = 0; t < 32; t++) {
        bool keep;
        if (dt == 0)      keep = ((const unsigned char*)mraw)[base + t] != 0;
        else if (dt == 1) keep = ((const int*)mraw)[base + t] != 0;
        else if (dt == 2) keep = ((const float*)mraw)[base + t] != 0.0f;
        else              keep = ((const unsigned short*)mraw)[base + t] != 0;
        if (keep) bits |= 1u << t;
    }
    g_mask[idx] = bits;
}

// ---------------------------------------------------------------------------
// fp32 -> fp16 round for BOTH weight matrices in one launch
// ---------------------------------------------------------------------------
__global__ void conv_round2(const float* __restrict__ a, __half* __restrict__ ha, int na,
                            const float* __restrict__ b, __half* __restrict__ hb, int nb) {
    int total = na + nb;
    for (int i = blockIdx.x * blockDim.x + threadIdx.x; i < total;
         i += gridDim.x * blockDim.x) {
        if (i < na) ha[i] = __float2half_rn(a[i]);
        else        hb[i - na] = __float2half_rn(b[i - na]);
    }
}

// x [B, K=768, N=16384] fp32 -> xT [B, N, K] fp16 single (transposed round)
__global__ void conv_xT(const float* __restrict__ x) {
    __shared__ float t[32][33];
    int bz = blockIdx.z;
    int n0 = blockIdx.x * 32, k0 = blockIdx.y * 32;
    int tx = threadIdx.x, ty = threadIdx.y;
    const float* xp = x + ((size_t)bz * DD + k0) * GP + n0;
    for (int i = ty; i < 32; i += 8) t[i][tx] = xp[(size_t)i * GP + tx];
    __syncthreads();
    for (int r = ty; r < 32; r += 8) {
        size_t o = ((size_t)bz * GP + n0 + r) * DD + k0 + tx;
        g_xT[o] = __float2half_rn(t[tx][r]);
    }
}

// ---------------------------------------------------------------------------
// Warp-MMA GEMM, cp.async 3-stage pipeline, occupancy 2 CTAs/SM:
//   C[bz] = A @ B[bz]^T (+ bias), pure fp16 1-product, output type OT.
// CTA 128x128, 8 warps (2m x 4n), warp tile 64x32, K-chunk 32.
// ---------------------------------------------------------------------------
#define GOA 0u
#define GOB 10240u
#define GST 20480u

template <typename OT>
__global__ __launch_bounds__(256, 2) void gemm_mma(
    const __half* __restrict__ A_, const __half* __restrict__ B_,
    OT* __restrict__ C, const float* __restrict__ bias, int Mtot)
{
    extern __shared__ char smem[];
    const int tid = threadIdx.x;
    const int wid = tid >> 5, lane = tid & 31;
    const int bz = blockIdx.z;
    const int col0 = blockIdx.x * 128;   // N block (fastest)
    const int row0 = blockIdx.y * 128;   // M block
    const __half* B = B_ + (size_t)bz * NT * KK;
    OT* Cb = C + (size_t)bz * (size_t)Mtot * NT;

    const int warpM = (wid & 1) * 64;
    const int warpN = (wid >> 1) * 32;
    const uint32_t sb = smem_u32(smem);

    const int lr = tid >> 1;
    const int lc = (tid & 1) * 2;
    const __half* pA = A_ + (size_t)(row0 + lr) * KK + lc * 8;
    const __half* pB = B  + (size_t)(col0 + lr) * KK + lc * 8;
    const uint32_t ss = lr * 80 + lc * 16;

    const int t0 = lane & 7, sel = lane >> 3;
    const uint32_t a_lrow = (warpM + t0 + ((sel & 1) << 3)) * 80 + ((sel >> 1) << 4);
    const uint32_t b_lrow = (warpN + t0 + ((sel >> 1) << 3)) * 80 + ((sel & 1) << 4);

    float acc[4][4][4];
#pragma unroll
    for (int i = 0; i < 4; i++)
#pragma unroll
        for (int j = 0; j < 4; j++)
#pragma unroll
            for (int r = 0; r < 4; r++) acc[i][j][r] = 0.0f;

    const int NCH = KK / 32;   // 24

    auto issue = [&](int c) {
        const uint32_t so = sb + (uint32_t)(c % 3) * GST + ss;
        const size_t ko = (size_t)c * 32;
        cpa16(so + GOA,      pA + ko);  cpa16(so + GOA + 16, pA + ko + 8);
        cpa16(so + GOB,      pB + ko);  cpa16(so + GOB + 16, pB + ko + 8);
    };

    issue(0); CPA_COMMIT();
    issue(1); CPA_COMMIT();

    for (int c = 0; c < NCH; c++) {
        if (c == NCH - 1) { CPA_WAIT0(); } else { CPA_WAIT1(); }
        __syncthreads();
        if (c + 2 < NCH) { issue(c + 2); CPA_COMMIT(); }

        const uint32_t so = sb + (uint32_t)(c % 3) * GST;
#pragma unroll
        for (int ks = 0; ks < 2; ks++) {
            uint32_t ah[4][4], bh[4][2];
#pragma unroll
            for (int mt = 0; mt < 4; mt++) {
                const uint32_t ad = so + a_lrow + mt * 16 * 80 + ks * 32;
                ldsm4(ah[mt][0], ah[mt][1], ah[mt][2], ah[mt][3], ad + GOA);
            }
#pragma unroll
            for (int ntp = 0; ntp < 2; ntp++) {
                const uint32_t bd = so + b_lrow + ntp * 16 * 80 + ks * 32;
                ldsm4(bh[2 * ntp][0], bh[2 * ntp][1], bh[2 * ntp + 1][0],
                      bh[2 * ntp + 1][1], bd + GOB);
            }
#pragma unroll
            for (int mt = 0; mt < 4; mt++)
#pragma unroll
                for (int nt = 0; nt < 4; nt++)
                    mma16816(acc[mt][nt], ah[mt], bh[nt]);
        }
    }

    const int gID = lane >> 2, tig = lane & 3;
#pragma unroll
    for (int mt = 0; mt < 4; mt++) {
#pragma unroll
        for (int half = 0; half < 2; half++) {
            const int row = row0 + warpM + mt * 16 + gID + half * 8;
            const float bv = bias ? __ldg(&bias[row]) : 0.0f;
            OT* cp = Cb + (size_t)row * NT + col0 + warpN + tig * 2;
#pragma unroll
            for (int nt = 0; nt < 4; nt++) {
                float v0 = acc[mt][nt][half * 2 + 0] + bv;
                float v1 = acc[mt][nt][half * 2 + 1] + bv;
                if (sizeof(OT) == 4) {
                    *(float2*)((float*)cp + nt * 8) = make_float2(v0, v1);
                } else {
                    __half2 hv = __floats2half2_rn(v0, v1);
                    *(__half2*)((__half*)cp + nt * 8) = hv;
                }
            }
        }
    }
}

// ---------------------------------------------------------------------------
// Tensor-core flash attention, OCCUPANCY 2: two CTAs per (b, h, g), each
// handling a 128-q-row half. 8 warps x 16 q-rows. Q (128 rows) + K (256) in
// smem [p][hd] fp16; V [hd][p]; mask half staged. Regs ~112 -> 2 CTAs/SM.
// ---------------------------------------------------------------------------
#define QKP 72                       // halfs per Q/K smem row  (144 B)
#define VP  264                      // halfs per V smem row    (528 B)
#define SQ_OFF 0
#define SK_OFF (128 * QKP * 2)                 // 18432
#define SV_OFF (SK_OFF + 256 * QKP * 2)        // 55296
#define SM_OFF (SV_OFF + 64 * VP * 2)          // 89088
#define ATT_SMEM (SM_OFF + 4096)               // 93184

__global__ __launch_bounds__(256, 2) void attn_mma(const __half* __restrict__ qkv)
{
    const int g = blockIdx.x;
    const int h = blockIdx.y >> 1, qh = blockIdx.y & 1;
    const int b = blockIdx.z;
    const int tid = threadIdx.x, wid = tid >> 5, lane = tid & 31;

    extern __shared__ char smn[];
    __half* Qs = (__half*)(smn + SQ_OFF);       // [128][QKP]
    __half* Ks = (__half*)(smn + SK_OFF);       // [256][QKP]
    __half* Vs = (__half*)(smn + SV_OFF);       // [64][VP]
    unsigned* Ms = (unsigned*)(smn + SM_OFF);   // [128][8]
    const uint32_t sb = smem_u32(smn);

    const __half* gq = qkv + ((size_t)b * E3D + h * HD) * GP + (size_t)g * PP;
    const __half* gk = gq + (size_t)DD * GP;
    const __half* gv = gq + (size_t)(2 * DD) * GP;

    // Q: this CTA's 128-row half, transposed scatter [hd][p] -> [p][hd]
    for (int idx = tid; idx < 64 * 64; idx += 256) {
        int hd = idx >> 6;
        int lp2 = (idx & 63) * 2;
        __half2 qv = *(const __half2*)(gq + (size_t)hd * GP + qh * 128 + lp2);
        Qs[lp2 * QKP + hd] = __low2half(qv);
        Qs[(lp2 + 1) * QKP + hd] = __high2half(qv);
    }
    // K: all 256 keys, transposed scatter
    for (int idx = tid; idx < 64 * 128; idx += 256) {
        int hd = idx >> 7;
        int p2 = (idx & 127) * 2;
        __half2 kv = *(const __half2*)(gk + (size_t)hd * GP + p2);
        Ks[p2 * QKP + hd] = __low2half(kv);
        Ks[(p2 + 1) * QKP + hd] = __high2half(kv);
    }
    // V: direct copy rows with pad
    for (int idx = tid; idx < 64 * 32; idx += 256) {
        int hd = idx >> 5, c = idx & 31;
        *(uint4*)(Vs + hd * VP + c * 8) = *(const uint4*)(gv + (size_t)hd * GP + c * 8);
    }
    // mask words for this q-half
    {
        const unsigned* mg = g_mask + ((size_t)g * PP + qh * 128) * 8;
        for (int idx = tid; idx < 1024; idx += 256) Ms[idx] = mg[idx];
    }
    __syncthreads();

    const int t0 = lane & 7, sel = lane >> 3;
    const int gID = lane >> 2, tig = lane & 3;
    const int rowbase = wid * 16;
    const float CC = 0.18033688011112042f;  // (1/8) * log2(e)

    // Q A-fragments: m16 x k64 (4 k-frags), resident all kernel
    uint32_t qa[4][4];
#pragma unroll
    for (int kf = 0; kf < 4; kf++) {
        uint32_t ad = sb + SQ_OFF +
            (uint32_t)(rowbase + t0 + (sel & 1) * 8) * (QKP * 2) +
            kf * 32 + (sel >> 1) * 16;
        ldsm4(qa[kf][0], qa[kf][1], qa[kf][2], qa[kf][3], ad);
    }

    float o[8][4];
#pragma unroll
    for (int nh = 0; nh < 8; nh++)
#pragma unroll
        for (int r = 0; r < 4; r++) o[nh][r] = 0.0f;
    float mrow[2] = {-INFINITY, -INFINITY};
    float lrow[2] = {0.0f, 0.0f};

    for (int kb = 0; kb < 8; kb++) {         // 8 blocks of 32 keys
        float S[4][4];
#pragma unroll
        for (int n4 = 0; n4 < 4; n4++)
#pragma unroll
            for (int r = 0; r < 4; r++) S[n4][r] = 0.0f;

#pragma unroll
        for (int np = 0; np < 2; np++) {
            uint32_t kbf[4][4];
#pragma unroll
            for (int kf = 0; kf < 4; kf++) {
                uint32_t ad = sb + SK_OFF +
                    (uint32_t)(kb * 32 + np * 16 + t0 + (sel >> 1) * 8) * (QKP * 2) +
                    kf * 32 + (sel & 1) * 16;
                ldsm4(kbf[kf][0], kbf[kf][1], kbf[kf][2], kbf[kf][3], ad);
            }
#pragma unroll
            for (int i = 0; i < 2; i++) {
                const int n4 = 2 * np + i;
#pragma unroll
                for (int kf = 0; kf < 4; kf++)
                    mma16816(S[n4], qa[kf], &kbf[kf][i * 2]);
            }
        }

        // scale + mask + online softmax (rows gID and gID+8 of this m16)
        const unsigned w0 = Ms[(rowbase + gID) * 8 + kb];
        const unsigned w1 = Ms[(rowbase + gID + 8) * 8 + kb];
        float mx0 = -INFINITY, mx1 = -INFINITY;
#pragma unroll
        for (int n4 = 0; n4 < 4; n4++) {
            const int bb0 = n4 * 8 + tig * 2;
            float s0 = ((w0 >> bb0) & 1u) ? S[n4][0] * CC : -1e30f;
            float s1 = ((w0 >> (bb0 + 1)) & 1u) ? S[n4][1] * CC : -1e30f;
            float s2 = ((w1 >> bb0) & 1u) ? S[n4][2] * CC : -1e30f;
            float s3 = ((w1 >> (bb0 + 1)) & 1u) ? S[n4][3] * CC : -1e30f;
            S[n4][0] = s0; S[n4][1] = s1;
            S[n4][2] = s2; S[n4][3] = s3;
            mx0 = fmaxf(mx0, fmaxf(s0, s1));
            mx1 = fmaxf(mx1, fmaxf(s2, s3));
        }
        mx0 = fmaxf(mx0, __shfl_xor_sync(0xffffffffu, mx0, 1));
        mx0 = fmaxf(mx0, __shfl_xor_sync(0xffffffffu, mx0, 2));
        mx1 = fmaxf(mx1, __shfl_xor_sync(0xffffffffu, mx1, 1));
        mx1 = fmaxf(mx1, __shfl_xor_sync(0xffffffffu, mx1, 2));

        const float mn0 = fmaxf(mrow[0], mx0);
        const float mn1 = fmaxf(mrow[1], mx1);
        const float al0 = fexp2(mrow[0] - mn0);
        const float al1 = fexp2(mrow[1] - mn1);
        mrow[0] = mn0; mrow[1] = mn1;

        float sum0 = 0.0f, sum1 = 0.0f;
#pragma unroll
        for (int n4 = 0; n4 < 4; n4++) {
            float p0 = fexp2(S[n4][0] - mn0);
            float p1 = fexp2(S[n4][1] - mn0);
            float p2 = fexp2(S[n4][2] - mn1);
            float p3 = fexp2(S[n4][3] - mn1);
            S[n4][0] = p0; S[n4][1] = p1;
            S[n4][2] = p2; S[n4][3] = p3;
            sum0 += p0 + p1;
            sum1 += p2 + p3;
        }
        sum0 += __shfl_xor_sync(0xffffffffu, sum0, 1);
        sum0 += __shfl_xor_sync(0xffffffffu, sum0, 2);
        sum1 += __shfl_xor_sync(0xffffffffu, sum1, 1);
        sum1 += __shfl_xor_sync(0xffffffffu, sum1, 2);
        lrow[0] = lrow[0] * al0 + sum0;
        lrow[1] = lrow[1] * al1 + sum1;
#pragma unroll
        for (int nh = 0; nh < 8; nh++) {
            o[nh][0] *= al0; o[nh][1] *= al0;
            o[nh][2] *= al1; o[nh][3] *= al1;
        }

        // P accumulator -> A fragments (half2 repack), k = 32 keys (2 kf)
        uint32_t pA[2][4];
#pragma unroll
        for (int kf = 0; kf < 2; kf++) {
            pA[kf][0] = h2pack(S[2 * kf][0],     S[2 * kf][1]);
            pA[kf][1] = h2pack(S[2 * kf][2],     S[2 * kf][3]);
            pA[kf][2] = h2pack(S[2 * kf + 1][0], S[2 * kf + 1][1]);
            pA[kf][3] = h2pack(S[2 * kf + 1][2], S[2 * kf + 1][3]);
        }

        // O += P V  (V^T fragments from Vs[hd][p]: n = hd, k = keys)
#pragma unroll
        for (int nh2 = 0; nh2 < 4; nh2++)
#pragma unroll
            for (int kf = 0; kf < 2; kf++) {
                uint32_t vb[4];
                uint32_t ad = sb + SV_OFF +
                    (uint32_t)(nh2 * 16 + t0 + (sel >> 1) * 8) * (VP * 2) +
                    kb * 64 + kf * 32 + (sel & 1) * 16;
                ldsm4(vb[0], vb[1], vb[2], vb[3], ad);
                mma16816(o[nh2 * 2 + 0], pA[kf], &vb[0]);
                mma16816(o[nh2 * 2 + 1], pA[kf], &vb[2]);
            }
    }

    // epilogue: normalize, fp16 round, transposed write into g_aT
#pragma unroll
    for (int hh = 0; hh < 2; hh++) {
        const int r = rowbase + gID + hh * 8;
        const int qrow = qh * 128 + r;
        const float inv = 1.0f / lrow[hh];
        __half* op = g_aT + ((size_t)b * GP + (size_t)g * PP + qrow) * DD + h * HD;
#pragma unroll
        for (int nh = 0; nh < 8; nh++) {
            __half2 hv = __floats2half2_rn(o[nh][hh * 2 + 0] * inv,
                                           o[nh][hh * 2 + 1] * inv);
            *(__half2*)(op + nh * 8 + tig * 2) = hv;
        }
    }
}

// ---------------------------------------------------------------------------
extern "C" void kernel_launch(void* const* d_in, const int* in_sizes, int n_in,
                              void* d_out, int out_size)
{
    const float* x      = (const float*)d_in[0];
    const void*  mask   = d_in[1];
    const float* w_qkv  = (const float*)d_in[2];
    const float* w_proj = (const float*)d_in[3];
    const float* b_proj = (const float*)d_in[4];
    float*       out    = (float*)d_out;

    __half *qkvbuf, *xt, *at, *wq, *wp;
    cudaGetSymbolAddress((void**)&qkvbuf, g_qkv);
    cudaGetSymbolAddress((void**)&xt, g_xT);
    cudaGetSymbolAddress((void**)&at, g_aT);
    cudaGetSymbolAddress((void**)&wq, g_wq);
    cudaGetSymbolAddress((void**)&wp, g_wp);

    // 0) mask dtype detection + bit packing
    detect_mask_dtype<<<1, 32>>>((const unsigned*)mask);
    pack_mask<<<(GG * PP * 8 + 255) / 256, 256>>>(mask);

    // 1) fp16 conversions: both weights in one launch + x^T transposed round
    conv_round2<<<1024, 256>>>(w_qkv, wq, E3D * DD, w_proj, wp, DD * DD);
    conv_xT<<<dim3(GP / 32, DD / 32, BB), dim3(32, 8)>>>(x);

    const int GEMM_SMEM = 3 * 20480;         // 60KB -> 2 CTAs/SM = 120KB
    cudaFuncSetAttribute((const void*)gemm_mma<__half>,
                         cudaFuncAttributeMaxDynamicSharedMemorySize, GEMM_SMEM);
    cudaFuncSetAttribute((const void*)gemm_mma<float>,
                         cudaFuncAttributeMaxDynamicSharedMemorySize, GEMM_SMEM);
    cudaFuncSetAttribute((const void*)attn_mma,
                         cudaFuncAttributeMaxDynamicSharedMemorySize, ATT_SMEM);

    // 2) QKV projection, 1-product fp16, fp16 output
    gemm_mma<__half><<<dim3(NT / 128, E3D / 128, BB), 256, GEMM_SMEM>>>(
        wq, xt, qkvbuf, nullptr, E3D);

    // 3) tensor-core flash attention, 2 CTAs per (b, h, g) -> occupancy 2
    attn_mma<<<dim3(GG, HH * 2, BB), 256, ATT_SMEM>>>(qkvbuf);

    // 4) output projection + bias, 1-product fp16, fp32 output
    gemm_mma<float><<<dim3(NT / 128, DD / 128, BB), 256, GEMM_SMEM>>>(
        wp, at, out, b_proj, DD);
}